// round 17
// baseline (speedup 1.0000x reference)
#include <cuda_runtime.h>
#include <cuda_bf16.h>
#include <cstdint>

#define NEG_INF (-1e30f)
#define BB 32
#define NN 256
#define KNB 20

// ---------------- mma.sync m16n8k16 bf16 + ldmatrix (baseline PTX) ----------
#define MMA16816(c, a0, a1, a2, a3, b0, b1) \
    asm volatile("mma.sync.aligned.m16n8k16.row.col.f32.bf16.bf16.f32 " \
        "{%0,%1,%2,%3}, {%4,%5,%6,%7}, {%8,%9}, {%0,%1,%2,%3};" \
        : "+f"((c)[0]), "+f"((c)[1]), "+f"((c)[2]), "+f"((c)[3]) \
        : "r"(a0), "r"(a1), "r"(a2), "r"(a3), "r"(b0), "r"(b1))

#define LDSM_X4(r0, r1, r2, r3, addr) \
    asm volatile("ldmatrix.sync.aligned.m8n8.x4.shared.b16 {%0,%1,%2,%3}, [%4];" \
        : "=r"(r0), "=r"(r1), "=r"(r2), "=r"(r3) : "r"(addr))

__device__ __forceinline__ uint32_t smem_u32(const void* p) {
    uint32_t a;
    asm("{ .reg .u64 t; cvta.to.shared.u64 t, %1; cvt.u32.u64 %0, t; }" : "=r"(a) : "l"(p));
    return a;
}

// ---------------- scratch globals ----------------
__device__ int            g_idx  [BB*NN*KNB];
__device__ float          g_H    [BB*NN*256];
__device__ __nv_bfloat16  g_w3hi [256*128];
__device__ __nv_bfloat16  g_w3lo [256*128];
__device__ __nv_bfloat16  g_w1hi [128*256];
__device__ __nv_bfloat16  g_w1lo [128*256];
__device__ float          g_w2T  [64*128];

// ---------------------------------------------------------------------------
// Kernel 0: weight prep (w2 transpose; w3 and fc1_w bf16 hi/lo splits)
// ---------------------------------------------------------------------------
__global__ __launch_bounds__(256) void transpose_kernel(
    const float* __restrict__ w2, const float* __restrict__ w3,
    const float* __restrict__ fc1w)
{
    int tid = blockIdx.x*256 + threadIdx.x;
    if (tid < 8192) { int c = tid >> 7, o = tid & 127; g_w2T[tid] = w2[o*64 + c]; }
    int t2 = tid - 8192;
    if (t2 >= 0 && t2 < 32768) {
        float v = w3[t2];
        __nv_bfloat16 h = __float2bfloat16(v);
        __nv_bfloat16 l = __float2bfloat16(v - __bfloat162float(h));
        g_w3hi[t2] = h; g_w3lo[t2] = l;
    }
    int t3 = tid - 40960;
    if (t3 >= 0 && t3 < 32768) {
        float v = fc1w[t3];
        __nv_bfloat16 h = __float2bfloat16(v);
        __nv_bfloat16 l = __float2bfloat16(v - __bfloat162float(h));
        g_w1hi[t3] = h; g_w1lo[t3] = l;
    }
}

// ---------------------------------------------------------------------------
// Kernel 1: kNN (one row/warp, redux argmax)
// ---------------------------------------------------------------------------
__global__ __launch_bounds__(256) void knn_kernel(const float* __restrict__ x) {
    __shared__ float xs0[NN], xs1[NN], xs2[NN], xxs[NN];
    int b      = blockIdx.x >> 5;
    int n_base = (blockIdx.x & 31) * 8;
    int tid = threadIdx.x;
    {
        float a0 = x[(b*NN + tid)*3 + 0];
        float a1 = x[(b*NN + tid)*3 + 1];
        float a2 = x[(b*NN + tid)*3 + 2];
        xs0[tid] = a0; xs1[tid] = a1; xs2[tid] = a2;
        xxs[tid] = a0*a0 + a1*a1 + a2*a2;
    }
    __syncthreads();
    int w = tid >> 5, lane = tid & 31;
    int i = n_base + w;

    float xi0 = xs0[i], xi1 = xs1[i], xi2 = xs2[i], xxi = xxs[i];
    unsigned m[8];
    #pragma unroll
    for (int t = 0; t < 8; t++) {
        int j = lane + 32*t;
        float dv = 2.f*(xi0*xs0[j] + xi1*xs1[j] + xi2*xs2[j]) - xxi - xxs[j];
        unsigned u = __float_as_uint(dv);
        m[t] = u ^ (unsigned)(((int)u >> 31) | 0x80000000);
    }

    int myj = 0;
    #pragma unroll 4
    for (int kk = 0; kk < KNB; kk++) {
        unsigned bv = m[0]; int bj = lane;
        #pragma unroll
        for (int t = 1; t < 8; t++)
            if (m[t] > bv) { bv = m[t]; bj = lane + 32*t; }
        unsigned vmax = __reduce_max_sync(0xffffffffu, bv);
        unsigned cand = (bv == vmax) ? (unsigned)bj : 0x7fffffffu;
        int jwin = (int)__reduce_min_sync(0xffffffffu, cand);
        if (lane == kk) myj = jwin;
        if ((jwin & 31) == lane) {
            int t = jwin >> 5;
            #pragma unroll
            for (int tt = 0; tt < 8; tt++) if (tt == t) m[tt] = 0u;
        }
    }
    if (lane < KNB) g_idx[(b*NN + i)*KNB + lane] = myj;
}

// ---------------------------------------------------------------------------
// Kernel 2: FUSED mlp (3 -> 64 -> 128 scalar, then 128 -> 256 via HMMA).
// (round-16 exact)
// ---------------------------------------------------------------------------
#define AHI_OFF 0
#define ALO_OFF 17408
#define BHI_OFF 34816
#define BLO_OFF 69632
#define XS_OFF  34816
#define H1S_OFF 35584
#define W2T_OFF 51968
#define S3H_OFF 104448
#define T3H_OFF 104960
#define MLP3H_SMEM 105472

__global__ __launch_bounds__(256, 2) void mlp3h_kernel(
    const float* __restrict__ x,
    const float* __restrict__ w1, const float* __restrict__ s1, const float* __restrict__ t1,
    const float* __restrict__ s2, const float* __restrict__ t2,
    const float* __restrict__ s3, const float* __restrict__ t3)
{
    extern __shared__ char smc[];
    int tid = threadIdx.x;
    int w = tid >> 5, lane = tid & 31;
    int g = lane >> 2, tig = lane & 3;
    int bid = blockIdx.x;
    int row0 = (bid >> 1) * 64;
    int oh = bid & 1;
    int b = row0 >> 8;
    int j0 = row0 & 255;

    float* xs   = (float*)(smc + XS_OFF);
    float* H1s  = (float*)(smc + H1S_OFF);
    float* W2Ts = (float*)(smc + W2T_OFF);

    if (tid < 192) xs[tid] = x[b*768 + j0*3 + tid];
    for (int e = tid; e < 2048; e += 256)
        ((float4*)W2Ts)[e] = ((const float4*)g_w2T)[e];
    if (tid < 128) {
        *(float*)(smc + S3H_OFF + tid*4) = s3[oh*128 + tid];
        *(float*)(smc + T3H_OFF + tid*4) = t3[oh*128 + tid];
    }
    __syncthreads();

    int rb = w * 8;

    {
        int o2 = lane + 32;
        float a0 = w1[lane*3], a1 = w1[lane*3+1], a2 = w1[lane*3+2];
        float b0 = w1[o2*3],   b1 = w1[o2*3+1],   b2 = w1[o2*3+2];
        float sa = s1[lane], ta = t1[lane], sb = s1[o2], tb = t1[o2];
        #pragma unroll
        for (int i = 0; i < 8; i++) {
            int row = rb + i;
            float x0 = xs[row*3], x1 = xs[row*3+1], x2 = xs[row*3+2];
            H1s[row*64 + lane]      = fmaxf(sa*(a0*x0 + a1*x1 + a2*x2) + ta, 0.f);
            H1s[row*64 + lane + 32] = fmaxf(sb*(b0*x0 + b1*x1 + b2*x2) + tb, 0.f);
        }
    }
    __syncwarp();

    {
        float acc[8][4];
        #pragma unroll
        for (int i = 0; i < 8; i++)
            #pragma unroll
            for (int k = 0; k < 4; k++) acc[i][k] = 0.f;
        #pragma unroll 8
        for (int c = 0; c < 64; c++) {
            float4 wv = *(const float4*)&W2Ts[c*128 + lane*4];
            #pragma unroll
            for (int i = 0; i < 8; i++) {
                float h = H1s[(rb+i)*64 + c];
                acc[i][0] += h*wv.x; acc[i][1] += h*wv.y;
                acc[i][2] += h*wv.z; acc[i][3] += h*wv.w;
            }
        }
        float sv[4], tv[4];
        #pragma unroll
        for (int k = 0; k < 4; k++) { sv[k] = s2[lane*4+k]; tv[k] = t2[lane*4+k]; }
        #pragma unroll
        for (int i = 0; i < 8; i++) {
            float o[4];
            #pragma unroll
            for (int k = 0; k < 4; k++)
                o[k] = fmaxf(sv[k]*acc[i][k] + tv[k], 0.f);
            __nv_bfloat16 h[4], l[4];
            #pragma unroll
            for (int k = 0; k < 4; k++) {
                h[k] = __float2bfloat16(o[k]);
                l[k] = __float2bfloat16(o[k] - __bfloat162float(h[k]));
            }
            int boff = (rb + i)*272 + lane*8;
            *(__nv_bfloat162*)(smc + AHI_OFF + boff)     = __halves2bfloat162(h[0], h[1]);
            *(__nv_bfloat162*)(smc + AHI_OFF + boff + 4) = __halves2bfloat162(h[2], h[3]);
            *(__nv_bfloat162*)(smc + ALO_OFF + boff)     = __halves2bfloat162(l[0], l[1]);
            *(__nv_bfloat162*)(smc + ALO_OFF + boff + 4) = __halves2bfloat162(l[2], l[3]);
        }
    }
    __syncthreads();

    for (int e = tid; e < 2048; e += 256) {
        int row = e >> 4, q = e & 15;
        *(uint4*)(smc + BHI_OFF + row*272 + q*16) =
            ((const uint4*)(g_w3hi + (oh*128 + row)*128))[q];
        *(uint4*)(smc + BLO_OFF + row*272 + q*16) =
            ((const uint4*)(g_w3lo + (oh*128 + row)*128))[q];
    }
    __syncthreads();

    int m0 = (w >> 1) * 16;
    int nb = (w & 1) * 64;

    uint32_t smb = smem_u32(smc);
    uint32_t a_row_off = (uint32_t)((m0 + (lane & 7) + ((lane >> 3) & 1)*8) * 272
                                    + (lane >> 4) * 16);
    uint32_t aaddr_hi = smb + AHI_OFF + a_row_off;
    uint32_t aaddr_lo = smb + ALO_OFF + a_row_off;
    uint32_t b_row_off = (uint32_t)((nb + ((lane >> 4) & 1)*8 + (lane & 7)) * 272
                                    + ((lane >> 3) & 1) * 16);
    uint32_t baddr_hi = smb + BHI_OFF + b_row_off;
    uint32_t baddr_lo = smb + BLO_OFF + b_row_off;

    float acc[8][4];
    #pragma unroll
    for (int nt = 0; nt < 8; nt++)
        #pragma unroll
        for (int k = 0; k < 4; k++) acc[nt][k] = 0.f;

    #pragma unroll
    for (int k0 = 0; k0 < 128; k0 += 16) {
        uint32_t ah0, ah1, ah2, ah3, al0, al1, al2, al3;
        LDSM_X4(ah0, ah1, ah2, ah3, aaddr_hi);
        LDSM_X4(al0, al1, al2, al3, aaddr_lo);
        aaddr_hi += 32; aaddr_lo += 32;
        #pragma unroll
        for (int p = 0; p < 4; p++) {
            uint32_t bh0, bh1, bh2, bh3, bl0, bl1, bl2, bl3;
            LDSM_X4(bh0, bh1, bh2, bh3, baddr_hi + p*4352u);
            LDSM_X4(bl0, bl1, bl2, bl3, baddr_lo + p*4352u);
            MMA16816(acc[2*p],   ah0, ah1, ah2, ah3, bh0, bh1);
            MMA16816(acc[2*p],   ah0, ah1, ah2, ah3, bl0, bl1);
            MMA16816(acc[2*p],   al0, al1, al2, al3, bh0, bh1);
            MMA16816(acc[2*p+1], ah0, ah1, ah2, ah3, bh2, bh3);
            MMA16816(acc[2*p+1], ah0, ah1, ah2, ah3, bl2, bl3);
            MMA16816(acc[2*p+1], al0, al1, al2, al3, bh2, bh3);
        }
        baddr_hi += 32; baddr_lo += 32;
    }

    #pragma unroll
    for (int nt = 0; nt < 8; nt++) {
        int ci = nb + nt*8 + 2*tig;
        float2 sv = *(const float2*)(smc + S3H_OFF + ci*4);
        float2 tv = *(const float2*)(smc + T3H_OFF + ci*4);
        float2 o0, o1;
        o0.x = fmaxf(sv.x*acc[nt][0] + tv.x, 0.f);
        o0.y = fmaxf(sv.y*acc[nt][1] + tv.y, 0.f);
        o1.x = fmaxf(sv.x*acc[nt][2] + tv.x, 0.f);
        o1.y = fmaxf(sv.y*acc[nt][3] + tv.y, 0.f);
        int col = oh*128 + ci;
        *(float2*)&g_H[(row0 + m0 + g)*256 + col]     = o0;
        *(float2*)&g_H[(row0 + m0 + g + 8)*256 + col] = o1;
    }
}

// ---------------------------------------------------------------------------
// Kernel 3: FUSED gather-max + fc1(HMMA bf16 hi/lo) + fc2.
// Round-16 base with: W1lo staged in phase A (overlap with gather),
// float2 gather loads (lane owns channels 2lane,2lane+1),
// fc2 on all 16 warps (o split + smem combine at Ps, dead A_lo region).
// ---------------------------------------------------------------------------
#define MFA_HI  0
#define MFA_LO  33792
#define MFHS    67584
#define MFW1HI  67584
#define MFW1LO  135168
#define MFW2    202752
#define MFB1    223232
#define MAXFC_SMEM 223744
#define MFPS    33792   // fc2 partials, overlays dead A_lo: [64 ch][41] f32

__global__ __launch_bounds__(512) void maxfc_kernel(
    const float* __restrict__ fc1_b,
    const float* __restrict__ fc2_w, const float* __restrict__ fc2_b,
    float* __restrict__ out)
{
    extern __shared__ char smc[];
    float* Hs  = (float*)(smc + MFHS);
    float* W2s = (float*)(smc + MFW2);
    int b = blockIdx.x >> 2, ct = blockIdx.x & 3;
    int tid = threadIdx.x;
    int w = tid >> 5, lane = tid & 31;
    int g = lane >> 2, tig = lane & 3;

    // ---- Phase A: stage Hs + W2s + fc1_b + W1lo (W1lo region is free now;
    //      its LDG latency overlaps the gather phase below)
    for (int e = tid; e < 4096; e += 512) {
        int j = e >> 4, q = e & 15;
        ((float4*)Hs)[e] = *(const float4*)(g_H + (b*256 + j)*256 + ct*64 + q*4);
    }
    for (int e = tid; e < 2048; e += 512) {
        int row = e >> 4, q = e & 15;
        *(uint4*)(smc + MFW1LO + row*528 + q*16) = ((const uint4*)(g_w1lo + row*256))[q];
        *(uint4*)(smc + MFW1LO + row*528 + (q+16)*16) =
            ((const uint4*)(g_w1lo + row*256))[q+16];
    }
    for (int e = tid; e < 1280; e += 512)
        ((float4*)W2s)[e] = ((const float4*)fc2_w)[e];
    if (tid < 128) *(float*)(smc + MFB1 + tid*4) = fc1_b[tid];
    __syncthreads();

    // ---- gather-max; lane owns channels (2lane, 2lane+1) via float2 loads
    #pragma unroll 2
    for (int t = 0; t < 16; t += 2) {
        int n0 = w*16 + t, n1 = n0 + 1;
        const int4* ip0 = (const int4*)(g_idx + (b*NN + n0)*KNB);
        const int4* ip1 = (const int4*)(g_idx + (b*NN + n1)*KNB);
        float a0 = NEG_INF, a1 = NEG_INF, c0 = NEG_INF, c1 = NEG_INF;
        int cb = 2*lane;
        #pragma unroll
        for (int q = 0; q < 5; q++) {
            int4 u = ip0[q];
            int4 v = ip1[q];
            float2 h;
            h = *(const float2*)&Hs[u.x*64 + cb]; a0 = fmaxf(a0, h.x); a1 = fmaxf(a1, h.y);
            h = *(const float2*)&Hs[v.x*64 + cb]; c0 = fmaxf(c0, h.x); c1 = fmaxf(c1, h.y);
            h = *(const float2*)&Hs[u.y*64 + cb]; a0 = fmaxf(a0, h.x); a1 = fmaxf(a1, h.y);
            h = *(const float2*)&Hs[v.y*64 + cb]; c0 = fmaxf(c0, h.x); c1 = fmaxf(c1, h.y);
            h = *(const float2*)&Hs[u.z*64 + cb]; a0 = fmaxf(a0, h.x); a1 = fmaxf(a1, h.y);
            h = *(const float2*)&Hs[v.z*64 + cb]; c0 = fmaxf(c0, h.x); c1 = fmaxf(c1, h.y);
            h = *(const float2*)&Hs[u.w*64 + cb]; a0 = fmaxf(a0, h.x); a1 = fmaxf(a1, h.y);
            h = *(const float2*)&Hs[v.w*64 + cb]; c0 = fmaxf(c0, h.x); c1 = fmaxf(c1, h.y);
        }
        // ch0 = 2lane gets (n0: a0, n1: c0); ch1 = 2lane+1 gets (n0: a1, n1: c1)
        __nv_bfloat16 h0 = __float2bfloat16(a0), h1 = __float2bfloat16(c0);
        __nv_bfloat16 l0 = __float2bfloat16(a0 - __bfloat162float(h0));
        __nv_bfloat16 l1 = __float2bfloat16(c0 - __bfloat162float(h1));
        *(__nv_bfloat162*)(smc + MFA_HI + cb*528 + n0*2) = __halves2bfloat162(h0, h1);
        *(__nv_bfloat162*)(smc + MFA_LO + cb*528 + n0*2) = __halves2bfloat162(l0, l1);
        __nv_bfloat16 h2 = __float2bfloat16(a1), h3 = __float2bfloat16(c1);
        __nv_bfloat16 l2 = __float2bfloat16(a1 - __bfloat162float(h2));
        __nv_bfloat16 l3 = __float2bfloat16(c1 - __bfloat162float(h3));
        *(__nv_bfloat162*)(smc + MFA_HI + (cb+1)*528 + n0*2) = __halves2bfloat162(h2, h3);
        *(__nv_bfloat162*)(smc + MFA_LO + (cb+1)*528 + n0*2) = __halves2bfloat162(l2, l3);
    }
    __syncthreads();

    // ---- Phase B: only W1hi left to stage (over dead Hs region)
    for (int e = tid; e < 4096; e += 512) {
        int row = e >> 5, q = e & 31;
        *(uint4*)(smc + MFW1HI + row*528 + q*16) = ((const uint4*)(g_w1hi + row*256))[q];
    }
    __syncthreads();

    // ---- fc1 HMMA: 16 warps = 4(m) x 4(n); warp covers 16 ch x 32 o; k = 256
    int m0 = (w >> 2) * 16;
    int nb = (w & 3) * 32;
    uint32_t smb = smem_u32(smc);
    uint32_t a_row_off = (uint32_t)((m0 + (lane & 7) + ((lane >> 3) & 1)*8) * 528
                                    + (lane >> 4) * 16);
    uint32_t aaddr_hi = smb + MFA_HI + a_row_off;
    uint32_t aaddr_lo = smb + MFA_LO + a_row_off;
    uint32_t b_row_off = (uint32_t)((nb + ((lane >> 4) & 1)*8 + (lane & 7)) * 528
                                    + ((lane >> 3) & 1) * 16);
    uint32_t baddr_hi = smb + MFW1HI + b_row_off;
    uint32_t baddr_lo = smb + MFW1LO + b_row_off;

    float acc[4][4];
    #pragma unroll
    for (int nt = 0; nt < 4; nt++)
        #pragma unroll
        for (int k = 0; k < 4; k++) acc[nt][k] = 0.f;

    #pragma unroll 4
    for (int k0 = 0; k0 < 256; k0 += 16) {
        uint32_t ah0, ah1, ah2, ah3, al0, al1, al2, al3;
        LDSM_X4(ah0, ah1, ah2, ah3, aaddr_hi);
        LDSM_X4(al0, al1, al2, al3, aaddr_lo);
        aaddr_hi += 32; aaddr_lo += 32;
        #pragma unroll
        for (int p = 0; p < 2; p++) {
            uint32_t bh0, bh1, bh2, bh3, bl0, bl1, bl2, bl3;
            LDSM_X4(bh0, bh1, bh2, bh3, baddr_hi + p*8448u);
            LDSM_X4(bl0, bl1, bl2, bl3, baddr_lo + p*8448u);
            MMA16816(acc[2*p],   ah0, ah1, ah2, ah3, bh0, bh1);
            MMA16816(acc[2*p],   ah0, ah1, ah2, ah3, bl0, bl1);
            MMA16816(acc[2*p],   al0, al1, al2, al3, bh0, bh1);
            MMA16816(acc[2*p+1], ah0, ah1, ah2, ah3, bh2, bh3);
            MMA16816(acc[2*p+1], ah0, ah1, ah2, ah3, bl2, bl3);
            MMA16816(acc[2*p+1], al0, al1, al2, al3, bh2, bh3);
        }
        baddr_hi += 32; baddr_lo += 32;
    }
    __syncthreads();   // A region dead; Gs/Ps overlay it

    // ---- epilogue: bias + relu into Gs[ch][129]
    float* Gs = (float*)smc;
    #pragma unroll
    for (int nt = 0; nt < 4; nt++) {
        int col = nb + nt*8 + 2*tig;
        float bv0 = *(const float*)(smc + MFB1 + col*4);
        float bv1 = *(const float*)(smc + MFB1 + col*4 + 4);
        Gs[(m0 + g)*129 + col]       = fmaxf(acc[nt][0] + bv0, 0.f);
        Gs[(m0 + g)*129 + col + 1]   = fmaxf(acc[nt][1] + bv1, 0.f);
        Gs[(m0 + g + 8)*129 + col]     = fmaxf(acc[nt][2] + bv0, 0.f);
        Gs[(m0 + g + 8)*129 + col + 1] = fmaxf(acc[nt][3] + bv1, 0.f);
    }
    __syncthreads();

    // ---- fc2 on all 16 warps: warp = (q-group wq: 8) x (o-half ohf: 2)
    {
        float* Ps = (float*)(smc + MFPS);   // [64 ch][41]
        int wq = w & 7, ohf = w >> 3;
        float acc2[2][5];
        #pragma unroll
        for (int h = 0; h < 2; h++)
            #pragma unroll
            for (int q = 0; q < 5; q++) acc2[h][q] = 0.f;
        int ob = ohf*64;
        #pragma unroll 4
        for (int o = ob; o < ob + 64; o++) {
            float ga = Gs[lane*129 + o];
            float gb = Gs[(lane + 32)*129 + o];
            #pragma unroll
            for (int q = 0; q < 5; q++) {
                float wv = W2s[(wq*5 + q)*128 + o];
                acc2[0][q] += ga*wv;
                acc2[1][q] += gb*wv;
            }
        }
        if (ohf == 1) {
            #pragma unroll
            for (int h = 0; h < 2; h++)
                #pragma unroll
                for (int q = 0; q < 5; q++)
                    Ps[(lane + h*32)*41 + wq*5 + q] = acc2[h][q];
        }
        __syncthreads();
        if (ohf == 0) {
            #pragma unroll
            for (int h = 0; h < 2; h++) {
                int cg = ct*64 + lane + h*32;
                #pragma unroll
                for (int q = 0; q < 5; q++)
                    out[(b*256 + cg)*40 + wq*5 + q] =
                        acc2[h][q] + Ps[(lane + h*32)*41 + wq*5 + q] + fc2_b[wq*5 + q];
            }
        }
    }
}

extern "C" void kernel_launch(void* const* d_in, const int* in_sizes, int n_in,
                              void* d_out, int out_size) {
    const float* x    = (const float*)d_in[0];
    const float* w1   = (const float*)d_in[1];
    const float* s1   = (const float*)d_in[2];
    const float* t1   = (const float*)d_in[3];
    const float* w2   = (const float*)d_in[4];
    const float* s2   = (const float*)d_in[5];
    const float* t2   = (const float*)d_in[6];
    const float* w3   = (const float*)d_in[7];
    const float* s3   = (const float*)d_in[8];
    const float* t3   = (const float*)d_in[9];
    const float* fc1w = (const float*)d_in[10];
    const float* fc1b = (const float*)d_in[11];
    const float* fc2w = (const float*)d_in[12];
    const float* fc2b = (const float*)d_in[13];
    float* out = (float*)d_out;

    cudaFuncSetAttribute(mlp3h_kernel, cudaFuncAttributeMaxDynamicSharedMemorySize, MLP3H_SMEM);
    cudaFuncSetAttribute(maxfc_kernel, cudaFuncAttributeMaxDynamicSharedMemorySize, MAXFC_SMEM);

    transpose_kernel<<<288, 256>>>(w2, w3, fc1w);
    knn_kernel<<<1024, 256>>>(x);
    mlp3h_kernel<<<256, 256, MLP3H_SMEM>>>(x, w1, s1, t1, s2, t2, s3, t3);
    maxfc_kernel<<<128, 512, MAXFC_SMEM>>>(fc1b, fc2w, fc2b, out);
}